// round 2
// baseline (speedup 1.0000x reference)
#include <cuda_runtime.h>
#include <math.h>
#include <stdint.h>

// ---------------------------------------------------------------------------
// Problem constants (ErnieImageAttention): B=2, S=4096, D=2048, 16 heads x 128
// ---------------------------------------------------------------------------
#define kB    2
#define kS    4096
#define kD    2048
#define kH    16
#define kHD   128
#define kT    (kB * kS)      /* 8192 tokens */
#define kEPS  1e-5f

#define BRr   128            /* flash-attn q rows per CTA  */
#define BCc   64             /* flash-attn kv rows per tile */

// Scratch (device-global: allocation-free rule)
__device__ float g_q[(size_t)kT * kD];
__device__ float g_k[(size_t)kT * kD];
__device__ float g_v[(size_t)kT * kD];
__device__ float g_attn[(size_t)kT * kD];

// ---------------------------------------------------------------------------
// Tiled fp32 GEMM: C[M,N] = A[M,K] @ B[K,N] (+bias). BM=BN=128, BK=16,
// 256 threads, 8x8 microtile split as 2x(4) strided chunks to reduce LDS
// bank conflicts.
// ---------------------------------------------------------------------------
__global__ __launch_bounds__(256) void gemm128_kernel(
    const float* __restrict__ A, const float* __restrict__ Bm,
    const float* __restrict__ bias, float* __restrict__ C,
    int M, int N, int K, int add_bias)
{
    __shared__ float As[16][132];   // As[k][m] (transposed)
    __shared__ float Bs[16][132];   // Bs[k][n]

    const int tid = threadIdx.x;
    const int tx = tid & 15;        // col group
    const int ty = tid >> 4;        // row group
    const int bm = blockIdx.y * 128;
    const int bn = blockIdx.x * 128;

    float acc[8][8];
#pragma unroll
    for (int i = 0; i < 8; ++i)
#pragma unroll
        for (int j = 0; j < 8; ++j) acc[i][j] = 0.f;

    const int arow = tid >> 2;           // 0..63
    const int acol = (tid & 3) << 2;     // 0,4,8,12
    const int br_  = tid >> 5;           // 0..7
    const int bc_  = (tid & 31) << 2;    // 0..124

    for (int k0 = 0; k0 < K; k0 += 16) {
#pragma unroll
        for (int i = 0; i < 2; ++i) {
            int r = arow + i * 64;
            float4 t4 = *(const float4*)(A + (size_t)(bm + r) * K + k0 + acol);
            As[acol + 0][r] = t4.x;
            As[acol + 1][r] = t4.y;
            As[acol + 2][r] = t4.z;
            As[acol + 3][r] = t4.w;
        }
#pragma unroll
        for (int i = 0; i < 2; ++i) {
            int r = br_ + i * 8;
            *(float4*)&Bs[r][bc_] = *(const float4*)(Bm + (size_t)(k0 + r) * N + bn + bc_);
        }
        __syncthreads();

#pragma unroll
        for (int k = 0; k < 16; ++k) {
            float a[8], b[8];
            *(float4*)&a[0] = *(const float4*)&As[k][ty * 4];
            *(float4*)&a[4] = *(const float4*)&As[k][64 + ty * 4];
            *(float4*)&b[0] = *(const float4*)&Bs[k][tx * 4];
            *(float4*)&b[4] = *(const float4*)&Bs[k][64 + tx * 4];
#pragma unroll
            for (int i = 0; i < 8; ++i)
#pragma unroll
                for (int j = 0; j < 8; ++j)
                    acc[i][j] += a[i] * b[j];
        }
        __syncthreads();
    }

    // epilogue: rows {ty*4+i, 64+ty*4+i}, cols {tx*4+j, 64+tx*4+j}
#pragma unroll
    for (int ii = 0; ii < 2; ++ii) {
#pragma unroll
        for (int i = 0; i < 4; ++i) {
            int r = bm + ii * 64 + ty * 4 + i;
            float* crow = C + (size_t)r * N + bn;
            float4 o0 = make_float4(acc[ii*4+i][0], acc[ii*4+i][1], acc[ii*4+i][2], acc[ii*4+i][3]);
            float4 o1 = make_float4(acc[ii*4+i][4], acc[ii*4+i][5], acc[ii*4+i][6], acc[ii*4+i][7]);
            if (add_bias) {
                const float* bp = bias + bn;
                o0.x += bp[tx*4+0];  o0.y += bp[tx*4+1];
                o0.z += bp[tx*4+2];  o0.w += bp[tx*4+3];
                o1.x += bp[64+tx*4+0]; o1.y += bp[64+tx*4+1];
                o1.z += bp[64+tx*4+2]; o1.w += bp[64+tx*4+3];
            }
            *(float4*)(crow + tx * 4)      = o0;
            *(float4*)(crow + 64 + tx * 4) = o1;
        }
    }
}

// ---------------------------------------------------------------------------
// Fused RMSNorm + RoPE on q and k (in place). One warp per (token, head).
// Lane holds dims {lane, lane+32, lane+64, lane+96} so rotary pairs
// (d, d+64) live in the same lane. Attention scale 1/sqrt(128) folded into q.
// ---------------------------------------------------------------------------
__global__ __launch_bounds__(256) void norm_rope_kernel(
    const float* __restrict__ freqs,
    const float* __restrict__ nqw,
    const float* __restrict__ nkw)
{
    const int gw   = (blockIdx.x * blockDim.x + threadIdx.x) >> 5;
    const int lane = threadIdx.x & 31;
    if (gw >= kT * kH) return;
    const int t = gw >> 4;                 // token
    const int s = t & (kS - 1);            // seq position
    float* qp = g_q + (size_t)gw * kHD;
    float* kp = g_k + (size_t)gw * kHD;
    const float* fp = freqs + (size_t)s * kHD;

    float qv[4], kv[4], cs[4], sn[4], wq_[4], wk_[4];
#pragma unroll
    for (int i = 0; i < 4; ++i) {
        int d = lane + i * 32;
        qv[i] = qp[d];
        kv[i] = kp[d];
        __sincosf(fp[d], &sn[i], &cs[i]);
        wq_[i] = nqw[d];
        wk_[i] = nkw[d];
    }
    float sq = 0.f, sk = 0.f;
#pragma unroll
    for (int i = 0; i < 4; ++i) { sq += qv[i]*qv[i]; sk += kv[i]*kv[i]; }
#pragma unroll
    for (int o = 16; o; o >>= 1) {
        sq += __shfl_xor_sync(0xffffffffu, sq, o);
        sk += __shfl_xor_sync(0xffffffffu, sk, o);
    }
    const float rq = rsqrtf(sq * (1.0f / 128.0f) + kEPS);
    const float rk = rsqrtf(sk * (1.0f / 128.0f) + kEPS);
#pragma unroll
    for (int i = 0; i < 4; ++i) { qv[i] *= rq * wq_[i]; kv[i] *= rk * wk_[i]; }

    const float qscale = 0.08838834764831845f;  // 1/sqrt(128)
    float qo[4], ko[4];
    // pairs: (idx0 <-> idx2) are dims (d, d+64); (idx1 <-> idx3) are (d+32, d+96)
    qo[0] = (qv[0]*cs[0] - qv[2]*sn[0]) * qscale;
    qo[1] = (qv[1]*cs[1] - qv[3]*sn[1]) * qscale;
    qo[2] = (qv[2]*cs[2] + qv[0]*sn[2]) * qscale;
    qo[3] = (qv[3]*cs[3] + qv[1]*sn[3]) * qscale;
    ko[0] =  kv[0]*cs[0] - kv[2]*sn[0];
    ko[1] =  kv[1]*cs[1] - kv[3]*sn[1];
    ko[2] =  kv[2]*cs[2] + kv[0]*sn[2];
    ko[3] =  kv[3]*cs[3] + kv[1]*sn[3];
#pragma unroll
    for (int i = 0; i < 4; ++i) {
        qp[lane + i * 32] = qo[i];
        kp[lane + i * 32] = ko[i];
    }
}

// ---------------------------------------------------------------------------
// Flash attention (non-causal), fp32. Grid: (S/BR, B*H). 256 threads.
// Q tile 128x128 + K tile stored k-major (transposed) in smem so both S and
// PV inner loops use vectorized fragment loads.
// ---------------------------------------------------------------------------
struct AttnSmem {
    float Qt[kHD][BRr + 4];    // Qt[k][row]   (transposed, scaled q)
    float Kt[kHD][BCc + 4];    // Kt[k][col]   (transposed)
    float Vs[BCc][kHD + 4];    // Vs[kvrow][dim]
    float Ps[BRr][BCc + 4];    // scores / probs
    float row_m[BRr];
    float row_l[BRr];
    float row_alpha[BRr];
};

__global__ __launch_bounds__(256) void attn_kernel()
{
    extern __shared__ char smem_raw[];
    AttnSmem& sm = *(AttnSmem*)smem_raw;

    const int tid   = threadIdx.x;
    const int qtile = blockIdx.x;          // 0..31
    const int bh    = blockIdx.y;          // 0..31
    const int b     = bh >> 4;
    const int h     = bh & 15;
    const size_t tok0 = (size_t)b * kS + (size_t)qtile * BRr;

    // ---- load Q tile (transposed into Qt) ----
    {
        int r  = tid >> 1;
        int c0 = (tid & 1) * 64;
        const float* src = g_q + ((tok0 + r) * kH + h) * kHD + c0;
#pragma unroll
        for (int i = 0; i < 16; ++i) {
            float4 v = *(const float4*)(src + i * 4);
            sm.Qt[c0 + i*4 + 0][r] = v.x;
            sm.Qt[c0 + i*4 + 1][r] = v.y;
            sm.Qt[c0 + i*4 + 2][r] = v.z;
            sm.Qt[c0 + i*4 + 3][r] = v.w;
        }
    }
    if (tid < BRr) { sm.row_m[tid] = -1e30f; sm.row_l[tid] = 0.f; }

    // S-stage mapping: rows s_rg*4+i (i<4), cols {s_cg*4+j, 32+s_cg*4+j} (j<4)
    const int s_rg = tid >> 3;     // 0..31
    const int s_cg = tid & 7;      // 0..7
    // PV-stage mapping: rows o_rg*8+i, cols {o_cg*4+j, 64+o_cg*4+j}
    const int o_rg = tid >> 4;     // 0..15
    const int o_cg = tid & 15;     // 0..15

    float Oacc[8][8];
#pragma unroll
    for (int i = 0; i < 8; ++i)
#pragma unroll
        for (int j = 0; j < 8; ++j) Oacc[i][j] = 0.f;

    const int red_r = tid >> 1;    // reduction row
    const int red_h = tid & 1;     // which half of 64

    for (int kt = 0; kt < kS / BCc; ++kt) {
        __syncthreads();   // protects Kt/Vs reuse (and covers Q-load on iter 0)

        // ---- load K (transposed) and V tiles ----
        {
            int r  = tid >> 2;           // 0..63 (kv row)
            int c0 = (tid & 3) * 32;
            const size_t ktok = (size_t)b * kS + (size_t)kt * BCc + r;
            const float* ksrc = g_k + (ktok * kH + h) * kHD + c0;
            const float* vsrc = g_v + (ktok * kH + h) * kHD + c0;
#pragma unroll
            for (int i = 0; i < 8; ++i) {
                float4 k4 = *(const float4*)(ksrc + i * 4);
                sm.Kt[c0 + i*4 + 0][r] = k4.x;
                sm.Kt[c0 + i*4 + 1][r] = k4.y;
                sm.Kt[c0 + i*4 + 2][r] = k4.z;
                sm.Kt[c0 + i*4 + 3][r] = k4.w;
                *(float4*)&sm.Vs[r][c0 + i * 4] = *(const float4*)(vsrc + i * 4);
            }
        }
        __syncthreads();

        // ---- S = Q @ K^T (scale already folded into q) ----
        float sacc[4][8];
#pragma unroll
        for (int i = 0; i < 4; ++i)
#pragma unroll
            for (int j = 0; j < 8; ++j) sacc[i][j] = 0.f;

#pragma unroll 2
        for (int k = 0; k < kHD; ++k) {
            float4 q4 = *(const float4*)&sm.Qt[k][s_rg * 4];
            float4 ka = *(const float4*)&sm.Kt[k][s_cg * 4];
            float4 kb = *(const float4*)&sm.Kt[k][32 + s_cg * 4];
            float qf[4] = {q4.x, q4.y, q4.z, q4.w};
            float kf[8] = {ka.x, ka.y, ka.z, ka.w, kb.x, kb.y, kb.z, kb.w};
#pragma unroll
            for (int i = 0; i < 4; ++i)
#pragma unroll
                for (int j = 0; j < 8; ++j)
                    sacc[i][j] += qf[i] * kf[j];
        }
#pragma unroll
        for (int i = 0; i < 4; ++i) {
            *(float4*)&sm.Ps[s_rg*4 + i][s_cg * 4] =
                make_float4(sacc[i][0], sacc[i][1], sacc[i][2], sacc[i][3]);
            *(float4*)&sm.Ps[s_rg*4 + i][32 + s_cg * 4] =
                make_float4(sacc[i][4], sacc[i][5], sacc[i][6], sacc[i][7]);
        }
        __syncthreads();

        // ---- online softmax bookkeeping: 2 threads per row ----
        {
            float* prow = &sm.Ps[red_r][red_h * 32];
            float mx = -1e30f;
#pragma unroll 8
            for (int j = 0; j < 32; ++j) mx = fmaxf(mx, prow[j]);
            mx = fmaxf(mx, __shfl_xor_sync(0xffffffffu, mx, 1));
            const float m_old = sm.row_m[red_r];            // lockstep read (same warp pair)
            const float m_new = fmaxf(m_old, mx);
            float ssum = 0.f;
#pragma unroll 8
            for (int j = 0; j < 32; ++j) {
                float e = __expf(prow[j] - m_new);
                prow[j] = e;
                ssum += e;
            }
            ssum += __shfl_xor_sync(0xffffffffu, ssum, 1);
            if (red_h == 0) {
                const float alpha = __expf(m_old - m_new);
                sm.row_alpha[red_r] = alpha;
                sm.row_m[red_r] = m_new;
                sm.row_l[red_r] = sm.row_l[red_r] * alpha + ssum;
            }
        }
        __syncthreads();

        // ---- O = O*alpha + P @ V ----
        float al[8];
#pragma unroll
        for (int i = 0; i < 8; ++i) al[i] = sm.row_alpha[o_rg * 8 + i];
#pragma unroll
        for (int i = 0; i < 8; ++i)
#pragma unroll
            for (int j = 0; j < 8; ++j) Oacc[i][j] *= al[i];

#pragma unroll 2
        for (int k = 0; k < BCc; ++k) {
            float4 va = *(const float4*)&sm.Vs[k][o_cg * 4];
            float4 vb = *(const float4*)&sm.Vs[k][64 + o_cg * 4];
            float vf[8] = {va.x, va.y, va.z, va.w, vb.x, vb.y, vb.z, vb.w};
            float pf[8];
#pragma unroll
            for (int i = 0; i < 8; ++i) pf[i] = sm.Ps[o_rg * 8 + i][k];
#pragma unroll
            for (int i = 0; i < 8; ++i)
#pragma unroll
                for (int j = 0; j < 8; ++j)
                    Oacc[i][j] += pf[i] * vf[j];
        }
    }

    // ---- finalize: divide by l, store ----
    float inv_l[8];
#pragma unroll
    for (int i = 0; i < 8; ++i) inv_l[i] = 1.0f / sm.row_l[o_rg * 8 + i];
#pragma unroll
    for (int i = 0; i < 8; ++i) {
        size_t tok = tok0 + (size_t)(o_rg * 8 + i);
        float* dst = g_attn + (tok * kH + h) * kHD;
        float4 w0 = make_float4(Oacc[i][0]*inv_l[i], Oacc[i][1]*inv_l[i],
                                Oacc[i][2]*inv_l[i], Oacc[i][3]*inv_l[i]);
        float4 w1 = make_float4(Oacc[i][4]*inv_l[i], Oacc[i][5]*inv_l[i],
                                Oacc[i][6]*inv_l[i], Oacc[i][7]*inv_l[i]);
        *(float4*)(dst + o_cg * 4)      = w0;
        *(float4*)(dst + 64 + o_cg * 4) = w1;
    }
}

// ---------------------------------------------------------------------------
// Launch: 3 QKV GEMMs -> norm+rope -> flash attention -> output projection
// ---------------------------------------------------------------------------
extern "C" void kernel_launch(void* const* d_in, const int* in_sizes, int n_in,
                              void* d_out, int out_size)
{
    (void)in_sizes; (void)n_in; (void)out_size;

    const float* hidden = (const float*)d_in[0];
    const float* freqs  = (const float*)d_in[1];
    const float* wq     = (const float*)d_in[2];
    const float* wk     = (const float*)d_in[3];
    const float* wv     = (const float*)d_in[4];
    const float* nqw    = (const float*)d_in[5];
    const float* nkw    = (const float*)d_in[6];
    const float* w_out  = (const float*)d_in[7];
    const float* b_out  = (const float*)d_in[8];
    float* out = (float*)d_out;

    float *qp = nullptr, *kp = nullptr, *vp = nullptr, *ap = nullptr;
    cudaGetSymbolAddress((void**)&qp, g_q);
    cudaGetSymbolAddress((void**)&kp, g_k);
    cudaGetSymbolAddress((void**)&vp, g_v);
    cudaGetSymbolAddress((void**)&ap, g_attn);

    cudaFuncSetAttribute(attn_kernel, cudaFuncAttributeMaxDynamicSharedMemorySize,
                         (int)sizeof(AttnSmem));

    dim3 gg(kD / 128, kT / 128);   // (16, 64)
    gemm128_kernel<<<gg, 256>>>(hidden, wq, nullptr, qp, kT, kD, kD, 0);
    gemm128_kernel<<<gg, 256>>>(hidden, wk, nullptr, kp, kT, kD, kD, 0);
    gemm128_kernel<<<gg, 256>>>(hidden, wv, nullptr, vp, kT, kD, kD, 0);

    norm_rope_kernel<<<(kT * kH * 32) / 256, 256>>>(freqs, nqw, nkw);

    attn_kernel<<<dim3(kS / BRr, kB * kH), 256, sizeof(AttnSmem)>>>();

    gemm128_kernel<<<gg, 256>>>(ap, w_out, b_out, out, kT, kD, kD, 1);
}

// round 6
// speedup vs baseline: 1.2471x; 1.2471x over previous
#include <cuda_runtime.h>
#include <cuda_bf16.h>
#include <math.h>
#include <stdint.h>

// ---------------------------------------------------------------------------
// Problem constants (ErnieImageAttention): B=2, S=4096, D=2048, 16 heads x 128
// ---------------------------------------------------------------------------
#define kB    2
#define kS    4096
#define kD    2048
#define kH    16
#define kHD   128
#define kT    (kB * kS)      /* 8192 tokens */
#define kEPS  1e-5f

#define BRr   128            /* flash-attn q rows per CTA  */
#define BCc   64             /* flash-attn kv rows per tile */

// Scratch (device-global: allocation-free rule)
__device__ float g_q[(size_t)kT * kD];
__device__ float g_k[(size_t)kT * kD];
__device__ float g_v[(size_t)kT * kD];
__device__ float g_attn[(size_t)kT * kD];
// bf16 hi/lo split operands
__device__ __nv_bfloat16 g_ahi[(size_t)kT * kD];
__device__ __nv_bfloat16 g_alo[(size_t)kT * kD];
__device__ __nv_bfloat16 g_wt[8][(size_t)kD * kD];   // 4 weights x (hi,lo), transposed [N][K]

// ---------------------------------------------------------------------------
// Helpers
// ---------------------------------------------------------------------------
__device__ __forceinline__ uint32_t smem_u32(const void* p) {
    uint32_t a;
    asm("{ .reg .u64 t; cvta.to.shared.u64 t, %1; cvt.u32.u64 %0, t; }" : "=r"(a) : "l"(p));
    return a;
}
__device__ __forceinline__ void cp16(uint32_t dst, const void* src) {
    asm volatile("cp.async.cg.shared.global [%0], [%1], 16;" :: "r"(dst), "l"(src));
}
#define CP_COMMIT() asm volatile("cp.async.commit_group;" ::: "memory")
#define CP_WAIT(n)  asm volatile("cp.async.wait_group %0;" :: "n"(n) : "memory")

// m16n8k16 bf16 MMA, fp32 accumulate (family-agnostic PTX, runs on sm_103 HMMA)
__device__ __forceinline__ void mma16816(float* d, const uint32_t* a, const uint32_t* b) {
    asm volatile("mma.sync.aligned.m16n8k16.row.col.f32.bf16.bf16.f32 "
        "{%0,%1,%2,%3}, {%4,%5,%6,%7}, {%8,%9}, {%0,%1,%2,%3};"
        : "+f"(d[0]), "+f"(d[1]), "+f"(d[2]), "+f"(d[3])
        : "r"(a[0]), "r"(a[1]), "r"(a[2]), "r"(a[3]), "r"(b[0]), "r"(b[1]));
}

// ---------------------------------------------------------------------------
// fp32 -> bf16 hi/lo split (elementwise, 4 elems/thread)
// ---------------------------------------------------------------------------
__global__ __launch_bounds__(256) void cvt_split_kernel(
    const float* __restrict__ src, __nv_bfloat16* __restrict__ hi,
    __nv_bfloat16* __restrict__ lo, int n4)
{
    int i = blockIdx.x * 256 + threadIdx.x;
    if (i >= n4) return;
    float4 v = ((const float4*)src)[i];
    __nv_bfloat16 h0 = __float2bfloat16(v.x), h1 = __float2bfloat16(v.y);
    __nv_bfloat16 h2 = __float2bfloat16(v.z), h3 = __float2bfloat16(v.w);
    __nv_bfloat16 l0 = __float2bfloat16(v.x - __bfloat162float(h0));
    __nv_bfloat16 l1 = __float2bfloat16(v.y - __bfloat162float(h1));
    __nv_bfloat16 l2 = __float2bfloat16(v.z - __bfloat162float(h2));
    __nv_bfloat16 l3 = __float2bfloat16(v.w - __bfloat162float(h3));
    ushort4 uh = make_ushort4(__bfloat16_as_ushort(h0), __bfloat16_as_ushort(h1),
                              __bfloat16_as_ushort(h2), __bfloat16_as_ushort(h3));
    ushort4 ul = make_ushort4(__bfloat16_as_ushort(l0), __bfloat16_as_ushort(l1),
                              __bfloat16_as_ushort(l2), __bfloat16_as_ushort(l3));
    ((ushort4*)hi)[i] = uh;
    ((ushort4*)lo)[i] = ul;
}

// ---------------------------------------------------------------------------
// W [K][N] fp32 -> transposed bf16 hi/lo [N][K]
// ---------------------------------------------------------------------------
__global__ __launch_bounds__(256) void tsp_split_kernel(
    const float* __restrict__ src, __nv_bfloat16* __restrict__ hiT,
    __nv_bfloat16* __restrict__ loT, int K, int N)
{
    __shared__ float ts[32][33];
    const int tx = threadIdx.x, ty = threadIdx.y;
#pragma unroll
    for (int j = 0; j < 4; ++j) {
        int y = blockIdx.y * 32 + ty + j * 8;
        ts[ty + j * 8][tx] = src[(size_t)y * N + blockIdx.x * 32 + tx];
    }
    __syncthreads();
#pragma unroll
    for (int j = 0; j < 4; ++j) {
        float v = ts[tx][ty + j * 8];
        int nrow = blockIdx.x * 32 + ty + j * 8;
        int kcol = blockIdx.y * 32 + tx;
        __nv_bfloat16 h = __float2bfloat16(v);
        __nv_bfloat16 l = __float2bfloat16(v - __bfloat162float(h));
        hiT[(size_t)nrow * K + kcol] = h;
        loT[(size_t)nrow * K + kcol] = l;
    }
}

// ---------------------------------------------------------------------------
// mma.sync GEMM (split bf16): C[M,N] = A[M,K] @ B^T, B stored [N][K] K-major.
// CTA 128x128, 8 warps (4x2) of 32x64 warp tiles, BK=32, cp.async 2-stage.
// ---------------------------------------------------------------------------
#define GBK    32
#define GPADH  40                  /* halves per smem row (32 + 8 pad) */
#define GROW32 20                  /* b32 words per smem row */
#define GTILE_B 10240              /* bytes per 128-row tile */
#define GSTG_B  40960              /* 4 tiles per stage */
#define GSMEM   (2 * GSTG_B)       /* 81920 B dynamic smem */

__global__ __launch_bounds__(256, 1) void gemm_mma_kernel(
    const __nv_bfloat16* __restrict__ Ahi, const __nv_bfloat16* __restrict__ Alo,
    const __nv_bfloat16* __restrict__ Bhi, const __nv_bfloat16* __restrict__ Blo,
    const float* __restrict__ bias, float* __restrict__ C,
    int M, int N, int K, int add_bias)
{
    extern __shared__ char smem[];
    const uint32_t sb = smem_u32(smem);
    const int tid = threadIdx.x, wid = tid >> 5, lane = tid & 31;
    const int g = lane >> 2, t = lane & 3;
    const int bm = blockIdx.y * 128, bn = blockIdx.x * 128;
    const int wm = (wid & 3) * 32, wn = (wid >> 2) * 64;

    float acc[2][8][4];
#pragma unroll
    for (int mt = 0; mt < 2; ++mt)
#pragma unroll
        for (int nt = 0; nt < 8; ++nt)
#pragma unroll
            for (int q = 0; q < 4; ++q) acc[mt][nt][q] = 0.f;

    const int NCH = K / GBK;

    // --- async stage loader: 4 tiles (Ahi, Alo, Bhi, Blo), 128r x 32h each ---
#define G_ISSUE(bufv, chv) do {                                                \
        int _k0 = (chv) * GBK;                                                 \
        uint32_t _d0 = sb + (bufv) * GSTG_B;                                   \
        _Pragma("unroll")                                                      \
        for (int _j = 0; _j < 2; ++_j) {                                       \
            int _seg = tid + _j * 256;                                         \
            int _row = _seg >> 2, _c4 = _seg & 3;                              \
            uint32_t _do_ = (uint32_t)(_row * 80 + _c4 * 16);                  \
            size_t _ao = (size_t)(bm + _row) * K + _k0 + _c4 * 8;              \
            size_t _bo = (size_t)(bn + _row) * K + _k0 + _c4 * 8;              \
            cp16(_d0 + 0 * GTILE_B + _do_, Ahi + _ao);                         \
            cp16(_d0 + 1 * GTILE_B + _do_, Alo + _ao);                         \
            cp16(_d0 + 2 * GTILE_B + _do_, Bhi + _bo);                         \
            cp16(_d0 + 3 * GTILE_B + _do_, Blo + _bo);                         \
        }                                                                      \
        CP_COMMIT();                                                           \
    } while (0)

    G_ISSUE(0, 0);

    for (int ch = 0; ch < NCH; ++ch) {
        const int buf = ch & 1;
        if (ch + 1 < NCH) { G_ISSUE(buf ^ 1, ch + 1); CP_WAIT(1); }
        else              { CP_WAIT(0); }
        __syncthreads();

        const uint32_t* Ah = (const uint32_t*)(smem + buf * GSTG_B);
        const uint32_t* Al = Ah + GTILE_B / 4;
        const uint32_t* Bh = Ah + 2 * (GTILE_B / 4);
        const uint32_t* Bl = Ah + 3 * (GTILE_B / 4);

#pragma unroll
        for (int ks = 0; ks < 2; ++ks) {
            const int kb = ks * 8;
            uint32_t ah[2][4], al[2][4], bh[8][2], bl[8][2];
#pragma unroll
            for (int mt = 0; mt < 2; ++mt) {
                int r0 = wm + mt * 16 + g;
                ah[mt][0] = Ah[r0 * GROW32 + kb + t];
                ah[mt][1] = Ah[(r0 + 8) * GROW32 + kb + t];
                ah[mt][2] = Ah[r0 * GROW32 + kb + 4 + t];
                ah[mt][3] = Ah[(r0 + 8) * GROW32 + kb + 4 + t];
                al[mt][0] = Al[r0 * GROW32 + kb + t];
                al[mt][1] = Al[(r0 + 8) * GROW32 + kb + t];
                al[mt][2] = Al[r0 * GROW32 + kb + 4 + t];
                al[mt][3] = Al[(r0 + 8) * GROW32 + kb + 4 + t];
            }
#pragma unroll
            for (int nt = 0; nt < 8; ++nt) {
                int n0 = wn + nt * 8 + g;
                bh[nt][0] = Bh[n0 * GROW32 + kb + t];
                bh[nt][1] = Bh[n0 * GROW32 + kb + 4 + t];
                bl[nt][0] = Bl[n0 * GROW32 + kb + t];
                bl[nt][1] = Bl[n0 * GROW32 + kb + 4 + t];
            }
            // hi*hi, then cross terms (independent D tiles inside each pass)
#pragma unroll
            for (int mt = 0; mt < 2; ++mt)
#pragma unroll
                for (int nt = 0; nt < 8; ++nt)
                    mma16816(acc[mt][nt], ah[mt], bh[nt]);
#pragma unroll
            for (int mt = 0; mt < 2; ++mt)
#pragma unroll
                for (int nt = 0; nt < 8; ++nt)
                    mma16816(acc[mt][nt], ah[mt], bl[nt]);
#pragma unroll
            for (int mt = 0; mt < 2; ++mt)
#pragma unroll
                for (int nt = 0; nt < 8; ++nt)
                    mma16816(acc[mt][nt], al[mt], bh[nt]);
        }
        __syncthreads();
    }
#undef G_ISSUE

    // --- epilogue: c0,c1 -> D[g][2t,2t+1]; c2,c3 -> D[g+8][2t,2t+1] ---
#pragma unroll
    for (int mt = 0; mt < 2; ++mt) {
#pragma unroll
        for (int nt = 0; nt < 8; ++nt) {
            int row0 = bm + wm + mt * 16 + g;
            int col  = bn + wn + nt * 8 + 2 * t;
            float2 v0 = make_float2(acc[mt][nt][0], acc[mt][nt][1]);
            float2 v1 = make_float2(acc[mt][nt][2], acc[mt][nt][3]);
            if (add_bias) {
                float2 bv = *(const float2*)(bias + col);
                v0.x += bv.x; v0.y += bv.y;
                v1.x += bv.x; v1.y += bv.y;
            }
            *(float2*)(C + (size_t)row0 * N + col)       = v0;
            *(float2*)(C + (size_t)(row0 + 8) * N + col) = v1;
        }
    }
}

// ---------------------------------------------------------------------------
// Fused RMSNorm + RoPE on q and k (in place). One warp per (token, head).
// ---------------------------------------------------------------------------
__global__ __launch_bounds__(256) void norm_rope_kernel(
    const float* __restrict__ freqs,
    const float* __restrict__ nqw,
    const float* __restrict__ nkw)
{
    const int gw   = (blockIdx.x * blockDim.x + threadIdx.x) >> 5;
    const int lane = threadIdx.x & 31;
    if (gw >= kT * kH) return;
    const int t = gw >> 4;                 // token
    const int s = t & (kS - 1);            // seq position
    float* qp = g_q + (size_t)gw * kHD;
    float* kp = g_k + (size_t)gw * kHD;
    const float* fp = freqs + (size_t)s * kHD;

    float qv[4], kv[4], cs[4], sn[4], wq_[4], wk_[4];
#pragma unroll
    for (int i = 0; i < 4; ++i) {
        int d = lane + i * 32;
        qv[i] = qp[d];
        kv[i] = kp[d];
        __sincosf(fp[d], &sn[i], &cs[i]);
        wq_[i] = nqw[d];
        wk_[i] = nkw[d];
    }
    float sq = 0.f, sk = 0.f;
#pragma unroll
    for (int i = 0; i < 4; ++i) { sq += qv[i]*qv[i]; sk += kv[i]*kv[i]; }
#pragma unroll
    for (int o = 16; o; o >>= 1) {
        sq += __shfl_xor_sync(0xffffffffu, sq, o);
        sk += __shfl_xor_sync(0xffffffffu, sk, o);
    }
    const float rq = rsqrtf(sq * (1.0f / 128.0f) + kEPS);
    const float rk = rsqrtf(sk * (1.0f / 128.0f) + kEPS);
#pragma unroll
    for (int i = 0; i < 4; ++i) { qv[i] *= rq * wq_[i]; kv[i] *= rk * wk_[i]; }

    const float qscale = 0.08838834764831845f;  // 1/sqrt(128)
    float qo[4], ko[4];
    qo[0] = (qv[0]*cs[0] - qv[2]*sn[0]) * qscale;
    qo[1] = (qv[1]*cs[1] - qv[3]*sn[1]) * qscale;
    qo[2] = (qv[2]*cs[2] + qv[0]*sn[2]) * qscale;
    qo[3] = (qv[3]*cs[3] + qv[1]*sn[3]) * qscale;
    ko[0] =  kv[0]*cs[0] - kv[2]*sn[0];
    ko[1] =  kv[1]*cs[1] - kv[3]*sn[1];
    ko[2] =  kv[2]*cs[2] + kv[0]*sn[2];
    ko[3] =  kv[3]*cs[3] + kv[1]*sn[3];
#pragma unroll
    for (int i = 0; i < 4; ++i) {
        qp[lane + i * 32] = qo[i];
        kp[lane + i * 32] = ko[i];
    }
}

// ---------------------------------------------------------------------------
// Flash attention (non-causal), fp32 SIMT. Grid: (S/BR, B*H). 256 threads.
// ---------------------------------------------------------------------------
struct AttnSmem {
    float Qt[kHD][BRr + 4];
    float Kt[kHD][BCc + 4];
    float Vs[BCc][kHD + 4];
    float Ps[BRr][BCc + 4];
    float row_m[BRr];
    float row_l[BRr];
    float row_alpha[BRr];
};

__global__ __launch_bounds__(256) void attn_kernel()
{
    extern __shared__ char smem_raw[];
    AttnSmem& sm = *(AttnSmem*)smem_raw;

    const int tid   = threadIdx.x;
    const int qtile = blockIdx.x;
    const int bh    = blockIdx.y;
    const int b     = bh >> 4;
    const int h     = bh & 15;
    const size_t tok0 = (size_t)b * kS + (size_t)qtile * BRr;

    {
        int r  = tid >> 1;
        int c0 = (tid & 1) * 64;
        const float* src = g_q + ((tok0 + r) * kH + h) * kHD + c0;
#pragma unroll
        for (int i = 0; i < 16; ++i) {
            float4 v = *(const float4*)(src + i * 4);
            sm.Qt[c0 + i*4 + 0][r] = v.x;
            sm.Qt[c0 + i*4 + 1][r] = v.y;
            sm.Qt[c0 + i*4 + 2][r] = v.z;
            sm.Qt[c0 + i*4 + 3][r] = v.w;
        }
    }
    if (tid < BRr) { sm.row_m[tid] = -1e30f; sm.row_l[tid] = 0.f; }

    const int s_rg = tid >> 3;
    const int s_cg = tid & 7;
    const int o_rg = tid >> 4;
    const int o_cg = tid & 15;

    float Oacc[8][8];
#pragma unroll
    for (int i = 0; i < 8; ++i)
#pragma unroll
        for (int j = 0; j < 8; ++j) Oacc[i][j] = 0.f;

    const int red_r = tid >> 1;
    const int red_h = tid & 1;

    for (int kt = 0; kt < kS / BCc; ++kt) {
        __syncthreads();

        {
            int r  = tid >> 2;
            int c0 = (tid & 3) * 32;
            const size_t ktok = (size_t)b * kS + (size_t)kt * BCc + r;
            const float* ksrc = g_k + (ktok * kH + h) * kHD + c0;
            const float* vsrc = g_v + (ktok * kH + h) * kHD + c0;
#pragma unroll
            for (int i = 0; i < 8; ++i) {
                float4 k4 = *(const float4*)(ksrc + i * 4);
                sm.Kt[c0 + i*4 + 0][r] = k4.x;
                sm.Kt[c0 + i*4 + 1][r] = k4.y;
                sm.Kt[c0 + i*4 + 2][r] = k4.z;
                sm.Kt[c0 + i*4 + 3][r] = k4.w;
                *(float4*)&sm.Vs[r][c0 + i * 4] = *(const float4*)(vsrc + i * 4);
            }
        }
        __syncthreads();

        float sacc[4][8];
#pragma unroll
        for (int i = 0; i < 4; ++i)
#pragma unroll
            for (int j = 0; j < 8; ++j) sacc[i][j] = 0.f;

#pragma unroll 2
        for (int k = 0; k < kHD; ++k) {
            float4 q4 = *(const float4*)&sm.Qt[k][s_rg * 4];
            float4 ka = *(const float4*)&sm.Kt[k][s_cg * 4];
            float4 kb = *(const float4*)&sm.Kt[k][32 + s_cg * 4];
            float qf[4] = {q4.x, q4.y, q4.z, q4.w};
            float kf[8] = {ka.x, ka.y, ka.z, ka.w, kb.x, kb.y, kb.z, kb.w};
#pragma unroll
            for (int i = 0; i < 4; ++i)
#pragma unroll
                for (int j = 0; j < 8; ++j)
                    sacc[i][j] += qf[i] * kf[j];
        }
#pragma unroll
        for (int i = 0; i < 4; ++i) {
            *(float4*)&sm.Ps[s_rg*4 + i][s_cg * 4] =
                make_float4(sacc[i][0], sacc[i][1], sacc[i][2], sacc[i][3]);
            *(float4*)&sm.Ps[s_rg*4 + i][32 + s_cg * 4] =
                make_float4(sacc[i][4], sacc[i][5], sacc[i][6], sacc[i][7]);
        }
        __syncthreads();

        {
            float* prow = &sm.Ps[red_r][red_h * 32];
            float mx = -1e30f;
#pragma unroll 8
            for (int j = 0; j < 32; ++j) mx = fmaxf(mx, prow[j]);
            mx = fmaxf(mx, __shfl_xor_sync(0xffffffffu, mx, 1));
            const float m_old = sm.row_m[red_r];
            const float m_new = fmaxf(m_old, mx);
            float ssum = 0.f;
#pragma unroll 8
            for (int j = 0; j < 32; ++j) {
                float e = __expf(prow[j] - m_new);
                prow[j] = e;
                ssum += e;
            }
            ssum += __shfl_xor_sync(0xffffffffu, ssum, 1);
            if (red_h == 0) {
                const float alpha = __expf(m_old - m_new);
                sm.row_alpha[red_r] = alpha;
                sm.row_m[red_r] = m_new;
                sm.row_l[red_r] = sm.row_l[red_r] * alpha + ssum;
            }
        }
        __syncthreads();

        float al[8];
#pragma unroll
        for (int i = 0; i < 8; ++i) al[i] = sm.row_alpha[o_rg * 8 + i];
#pragma unroll
        for (int i = 0; i < 8; ++i)
#pragma unroll
            for (int j = 0; j < 8; ++j) Oacc[i][j] *= al[i];

#pragma unroll 2
        for (int k = 0; k < BCc; ++k) {
            float4 va = *(const float4*)&sm.Vs[k][o_cg * 4];
            float4 vb = *(const float4*)&sm.Vs[k][64 + o_cg * 4];
            float vf[8] = {va.x, va.y, va.z, va.w, vb.x, vb.y, vb.z, vb.w};
            float pf[8];
#pragma unroll
            for (int i = 0; i < 8; ++i) pf[i] = sm.Ps[o_rg * 8 + i][k];
#pragma unroll
            for (int i = 0; i < 8; ++i)
#pragma unroll
                for (int j = 0; j < 8; ++j)
                    Oacc[i][j] += pf[i] * vf[j];
        }
    }

    float inv_l[8];
#pragma unroll
    for (int i = 0; i < 8; ++i) inv_l[i] = 1.0f / sm.row_l[o_rg * 8 + i];
#pragma unroll
    for (int i = 0; i < 8; ++i) {
        size_t tok = tok0 + (size_t)(o_rg * 8 + i);
        float* dst = g_attn + (tok * kH + h) * kHD;
        float4 w0 = make_float4(Oacc[i][0]*inv_l[i], Oacc[i][1]*inv_l[i],
                                Oacc[i][2]*inv_l[i], Oacc[i][3]*inv_l[i]);
        float4 w1 = make_float4(Oacc[i][4]*inv_l[i], Oacc[i][5]*inv_l[i],
                                Oacc[i][6]*inv_l[i], Oacc[i][7]*inv_l[i]);
        *(float4*)(dst + o_cg * 4)      = w0;
        *(float4*)(dst + 64 + o_cg * 4) = w1;
    }
}

// ---------------------------------------------------------------------------
// Launch sequence
// ---------------------------------------------------------------------------
extern "C" void kernel_launch(void* const* d_in, const int* in_sizes, int n_in,
                              void* d_out, int out_size)
{
    (void)in_sizes; (void)n_in; (void)out_size;

    const float* hidden = (const float*)d_in[0];
    const float* freqs  = (const float*)d_in[1];
    const float* wq     = (const float*)d_in[2];
    const float* wk     = (const float*)d_in[3];
    const float* wv     = (const float*)d_in[4];
    const float* nqw    = (const float*)d_in[5];
    const float* nkw    = (const float*)d_in[6];
    const float* w_out  = (const float*)d_in[7];
    const float* b_out  = (const float*)d_in[8];
    float* out = (float*)d_out;

    float *qp = nullptr, *kp = nullptr, *vp = nullptr, *ap = nullptr;
    __nv_bfloat16 *ahi = nullptr, *alo = nullptr, *wt = nullptr;
    cudaGetSymbolAddress((void**)&qp, g_q);
    cudaGetSymbolAddress((void**)&kp, g_k);
    cudaGetSymbolAddress((void**)&vp, g_v);
    cudaGetSymbolAddress((void**)&ap, g_attn);
    cudaGetSymbolAddress((void**)&ahi, g_ahi);
    cudaGetSymbolAddress((void**)&alo, g_alo);
    cudaGetSymbolAddress((void**)&wt, g_wt);
    const size_t WSZ = (size_t)kD * kD;
    __nv_bfloat16* w0h = wt + 0 * WSZ;  __nv_bfloat16* w0l = wt + 1 * WSZ;
    __nv_bfloat16* w1h = wt + 2 * WSZ;  __nv_bfloat16* w1l = wt + 3 * WSZ;
    __nv_bfloat16* w2h = wt + 4 * WSZ;  __nv_bfloat16* w2l = wt + 5 * WSZ;
    __nv_bfloat16* w3h = wt + 6 * WSZ;  __nv_bfloat16* w3l = wt + 7 * WSZ;

    cudaFuncSetAttribute(attn_kernel, cudaFuncAttributeMaxDynamicSharedMemorySize,
                         (int)sizeof(AttnSmem));
    cudaFuncSetAttribute(gemm_mma_kernel, cudaFuncAttributeMaxDynamicSharedMemorySize,
                         GSMEM);

    const int n4h = (kT * kD) / 4;
    // split hidden states into bf16 hi/lo
    cvt_split_kernel<<<(n4h + 255) / 256, 256>>>(hidden, ahi, alo, n4h);
    // transpose+split weights -> [N][K]
    dim3 tg(kD / 32, kD / 32), tb(32, 8);
    tsp_split_kernel<<<tg, tb>>>(wq,    w0h, w0l, kD, kD);
    tsp_split_kernel<<<tg, tb>>>(wk,    w1h, w1l, kD, kD);
    tsp_split_kernel<<<tg, tb>>>(wv,    w2h, w2l, kD, kD);
    tsp_split_kernel<<<tg, tb>>>(w_out, w3h, w3l, kD, kD);

    // QKV projections (tensor core via mma.sync)
    dim3 gg(kD / 128, kT / 128);   // (16, 64)
    gemm_mma_kernel<<<gg, 256, GSMEM>>>(ahi, alo, w0h, w0l, nullptr, qp, kT, kD, kD, 0);
    gemm_mma_kernel<<<gg, 256, GSMEM>>>(ahi, alo, w1h, w1l, nullptr, kp, kT, kD, kD, 0);
    gemm_mma_kernel<<<gg, 256, GSMEM>>>(ahi, alo, w2h, w2l, nullptr, vp, kT, kD, kD, 0);

    norm_rope_kernel<<<(kT * kH * 32) / 256, 256>>>(freqs, nqw, nkw);

    attn_kernel<<<dim3(kS / BRr, kB * kH), 256, sizeof(AttnSmem)>>>();

    // split attention output, then output projection (+bias)
    cvt_split_kernel<<<(n4h + 255) / 256, 256>>>(ap, ahi, alo, n4h);
    gemm_mma_kernel<<<gg, 256, GSMEM>>>(ahi, alo, w3h, w3l, b_out, out, kT, kD, kD, 1);
}